// round 5
// baseline (speedup 1.0000x reference)
#include <cuda_runtime.h>
#include <math.h>

// Problem dims
#define Ln  8
#define Tn  512
#define Hn  128
#define Bn  64
#define G4  512     // 4*H
#define Vn  65
#define On  65

#define NC   32     // gate columns per CTA
#define CPL  16     // CTAs per layer
#define NTHR 256

#define OUT_MAIN   (Bn*Tn*On)          // outputs [B][T][OUT]
#define OUT_H_BASE (OUT_MAIN)          // hT [L][B][H]
#define OUT_C_BASE (OUT_MAIN + Ln*Bn*Hn)

// Scratch (allocation-free rule: __device__ globals)
__device__ float    g_hseq[Ln*Tn*Hn*Bn];   // [l][t][u][b]
__device__ float    g_tok[Vn*G4];          // embed@w_ih[0] + b_ih0 + b_hh0
__device__ int      g_xT[Tn*Bn];           // tokens transposed [t][b]
__device__ unsigned g_cnt[Ln*Tn];          // completion counters

__device__ __forceinline__ unsigned ld_acq(const unsigned* p){
    unsigned v;
    asm volatile("ld.acquire.gpu.global.u32 %0, [%1];" : "=r"(v) : "l"(p) : "memory");
    return v;
}
__device__ __forceinline__ void red_rel_add(unsigned* p){
    asm volatile("red.release.gpu.global.add.u32 [%0], 1;" :: "l"(p) : "memory");
}
__device__ __forceinline__ float fsig(float x){
    return __fdividef(1.f, 1.f + __expf(-x));
}
__device__ __forceinline__ float ftanh(float x){
    return 1.f - __fdividef(2.f, __expf(2.f*x) + 1.f);
}
__device__ __forceinline__ unsigned long long pk2(float lo, float hi){
    unsigned l = __float_as_uint(lo), h = __float_as_uint(hi);
    return ((unsigned long long)h << 32) | (unsigned long long)l;
}
__device__ __forceinline__ float lo32(unsigned long long v){ return __uint_as_float((unsigned)v); }
__device__ __forceinline__ float hi32(unsigned long long v){ return __uint_as_float((unsigned)(v >> 32)); }

// ---------------------------------------------------------------------------
// Reset flags + transpose tokens
__global__ void k_reset(const int* __restrict__ x){
    int i = blockIdx.x*blockDim.x + threadIdx.x;
    if (i < Ln*Tn) g_cnt[i] = 0u;
    if (i < Tn*Bn){
        int t = i / Bn, b = i % Bn;
        g_xT[i] = x[b*Tn + t];
    }
}

// ---------------------------------------------------------------------------
// Token gate table for layer 0
__global__ void k_token(const float* __restrict__ embed, const float* __restrict__ w_ih,
                        const float* __restrict__ b_ih, const float* __restrict__ b_hh){
    __shared__ float e[Hn];
    int v = blockIdx.x, c = threadIdx.x;
    if (c < Hn) e[c] = embed[v*Hn + c];
    __syncthreads();
    float acc = b_ih[c] + b_hh[c];
#pragma unroll 8
    for (int k = 0; k < Hn; ++k) acc += e[k] * w_ih[k*G4 + c];
    g_tok[v*G4 + c] = acc;
}

// ---------------------------------------------------------------------------
// Persistent wavefront LSTM: 8 layers x 16 CTAs, all co-resident.
// Packed-fp32 (fma.rn.f32x2) GEMM: W pre-duplicated in SMEM as {w,w} pairs.
__global__ void __launch_bounds__(NTHR, 1) k_lstm(
    const float* __restrict__ w_ih, const float* __restrict__ b_ih,
    const float* __restrict__ w_hh, const float* __restrict__ b_hh,
    float* __restrict__ out)
{
    extern __shared__ float sm[];
    float* Wdup = sm;                  // [256][64]  {w,w}-duplicated column slice (64 KB)
    float* Z    = sm + 16384;          // [256][64]  [inp; h_prev], b-contiguous  (64 KB)
    float* Gsm  = Z  + 16384;          // [32][64]   gate preactivations          (8 KB)
    float* Bsm  = Gsm + 2048;          // [32]       folded biases

    const int layer = blockIdx.x >> 4;
    const int gidx  = blockIdx.x & 15;     // unit group: units [8*gidx, 8*gidx+8)
    const int tid   = threadIdx.x;

    // Stage duplicated weight slice. local col cl: gate = cl>>3, ul = cl&7
    for (int i = tid; i < 256*NC; i += NTHR){
        int k  = i >> 5, cl = i & 31;
        int col = ((cl >> 3) << 7) + (gidx << 3) + (cl & 7);
        float w = (k < Hn) ? w_ih[(layer*Hn + k)*G4 + col]
                           : w_hh[(layer*Hn + (k-Hn))*G4 + col];
        *(float2*)&Wdup[(k << 6) + (cl << 1)] = make_float2(w, w);
    }
    if (tid < NC){
        int col = ((tid >> 3) << 7) + (gidx << 3) + (tid & 7);
        Bsm[tid] = b_ih[layer*G4 + col] + b_hh[layer*G4 + col];
    }
    __syncthreads();

    // GEMM microtile: 2 local cols x 4 batch per thread
    const int c0  = (tid >> 4) * 2;        // local col, even
    const int b0  = (tid & 15) * 4;
    const int gc0 = ((c0 >> 3) << 7) + (gidx << 3) + (c0 & 7);
    const int gc1 = gc0 + 1;               // c0 even -> same gate

    // Elementwise mapping: 2 (unit,b) pairs per thread
    const int p0   = tid * 2;
    const int e_ul = p0 >> 6;              // 0..7
    const int e_b  = p0 & 63;              // even
    const int e_u  = (gidx << 3) + e_ul;

    float cst0 = 0.f, cst1 = 0.f;

    unsigned* cnt_own   = &g_cnt[layer*Tn];
    unsigned* cnt_below = (layer > 0) ? &g_cnt[(layer-1)*Tn] : nullptr;

    for (int t = 0; t < Tn; ++t){
        // ---- wait for dependencies (parallel waits on two threads) ----
        if (tid == 0 && layer > 0){ while (ld_acq(&cnt_below[t]) < CPL) __nanosleep(16); }
        if (tid == 32 && t > 0)   { while (ld_acq(&cnt_own[t-1]) < CPL) __nanosleep(16); }
        __syncthreads();

        // ---- load Z = [inp(128x64) ; h_prev(128x64)] ----
        if (layer > 0){
            const float4* s = (const float4*)&g_hseq[((layer-1)*Tn + t)*Hn*Bn];
            float4* d = (float4*)Z;
            for (int i = tid; i < 2048; i += NTHR) d[i] = s[i];
        }
        if (t > 0){
            const float4* s = (const float4*)&g_hseq[(layer*Tn + (t-1))*Hn*Bn];
            float4* d = (float4*)(Z + Hn*Bn);
            for (int i = tid; i < 2048; i += NTHR) d[i] = s[i];
        } else {
            float4 zz = make_float4(0.f,0.f,0.f,0.f);
            float4* d = (float4*)(Z + Hn*Bn);
            for (int i = tid; i < 2048; i += NTHR) d[i] = zz;
        }
        __syncthreads();

        // ---- gate GEMM microtile (packed f32x2) ----
        // acc lanes: low = batch b, high = batch b+1
        unsigned long long a0a, a0b, a1a, a1b;
        if (layer == 0){
            int tb = t*Bn + b0;
            int tk0 = g_xT[tb+0], tk1 = g_xT[tb+1], tk2 = g_xT[tb+2], tk3 = g_xT[tb+3];
            a0a = pk2(g_tok[tk0*G4+gc0], g_tok[tk1*G4+gc0]);
            a0b = pk2(g_tok[tk2*G4+gc0], g_tok[tk3*G4+gc0]);
            a1a = pk2(g_tok[tk0*G4+gc1], g_tok[tk1*G4+gc1]);
            a1b = pk2(g_tok[tk2*G4+gc1], g_tok[tk3*G4+gc1]);
        } else {
            float bb0 = Bsm[c0], bb1 = Bsm[c0+1];
            a0a = pk2(bb0, bb0); a0b = a0a;
            a1a = pk2(bb1, bb1); a1b = a1a;
        }

        const int kstart = (layer == 0) ? Hn : 0;
#pragma unroll 8
        for (int k = kstart; k < 256; ++k){
            ulonglong2 z2 = *(const ulonglong2*)&Z[(k << 6) + b0];        // {b0,b0+1},{b0+2,b0+3}
            ulonglong2 w2 = *(const ulonglong2*)&Wdup[(k << 6) + (c0 << 1)]; // {w0,w0},{w1,w1}
            asm("fma.rn.f32x2 %0, %1, %2, %0;" : "+l"(a0a) : "l"(w2.x), "l"(z2.x));
            asm("fma.rn.f32x2 %0, %1, %2, %0;" : "+l"(a0b) : "l"(w2.x), "l"(z2.y));
            asm("fma.rn.f32x2 %0, %1, %2, %0;" : "+l"(a1a) : "l"(w2.y), "l"(z2.x));
            asm("fma.rn.f32x2 %0, %1, %2, %0;" : "+l"(a1b) : "l"(w2.y), "l"(z2.y));
        }

        *(float4*)&Gsm[ c0   *Bn + b0] = make_float4(lo32(a0a), hi32(a0a), lo32(a0b), hi32(a0b));
        *(float4*)&Gsm[(c0+1)*Bn + b0] = make_float4(lo32(a1a), hi32(a1a), lo32(a1b), hi32(a1b));
        __syncthreads();

        // ---- elementwise LSTM cell (2 pairs per thread) ----
        float gi0 = Gsm[( 0+e_ul)*Bn + e_b    ];
        float gf0 = Gsm[( 8+e_ul)*Bn + e_b    ];
        float gg0 = Gsm[(16+e_ul)*Bn + e_b    ];
        float go0 = Gsm[(24+e_ul)*Bn + e_b    ];
        float gi1 = Gsm[( 0+e_ul)*Bn + e_b + 1];
        float gf1 = Gsm[( 8+e_ul)*Bn + e_b + 1];
        float gg1 = Gsm[(16+e_ul)*Bn + e_b + 1];
        float go1 = Gsm[(24+e_ul)*Bn + e_b + 1];

        float i0 = fsig(gi0), f0 = fsig(gf0), o0 = fsig(go0), g0 = ftanh(gg0);
        float i1 = fsig(gi1), f1 = fsig(gf1), o1 = fsig(go1), g1 = ftanh(gg1);
        cst0 = f0*cst0 + i0*g0;
        cst1 = f1*cst1 + i1*g1;
        float h0 = o0 * ftanh(cst0);
        float h1 = o1 * ftanh(cst1);

        *(float2*)&g_hseq[(layer*Tn + t)*Hn*Bn + e_u*Bn + e_b] = make_float2(h0, h1);

        if (t == Tn-1){
            out[OUT_H_BASE + (layer*Bn + e_b    )*Hn + e_u] = h0;
            out[OUT_H_BASE + (layer*Bn + e_b + 1)*Hn + e_u] = h1;
            out[OUT_C_BASE + (layer*Bn + e_b    )*Hn + e_u] = cst0;
            out[OUT_C_BASE + (layer*Bn + e_b + 1)*Hn + e_u] = cst1;
        }
        __syncthreads();   // all stores done (and Z/Gsm safe for reuse)
        if (tid == 0) red_rel_add(&cnt_own[t]);
    }
}

// ---------------------------------------------------------------------------
// Output projection: outputs[b][t][o] = h7[t][:,b] . w_out[:,o] + b_out[o]
__global__ void k_out(const float* __restrict__ w_out, const float* __restrict__ b_out,
                      float* __restrict__ out){
    extern __shared__ float sm[];
    float* Hs = sm;            // [128][64]
    float* Ws = sm + 8192;     // [128][65]
    int t = blockIdx.x, tid = threadIdx.x;

    const float4* s = (const float4*)&g_hseq[(7*Tn + t)*Hn*Bn];
    for (int i = tid; i < 2048; i += 256) ((float4*)Hs)[i] = s[i];
    for (int i = tid; i < Hn*On; i += 256) Ws[i] = w_out[i];
    __syncthreads();

    int b = tid & 63, og = tid >> 6;
    for (int o = og; o < On; o += 4){
        float acc = b_out[o];
#pragma unroll 8
        for (int k = 0; k < Hn; ++k) acc += Hs[k*Bn + b] * Ws[k*On + o];
        out[(b*Tn + t)*On + o] = acc;
    }
}

// ---------------------------------------------------------------------------
extern "C" void kernel_launch(void* const* d_in, const int* in_sizes, int n_in,
                              void* d_out, int out_size)
{
    const int*   x     = (const int*)  d_in[0];
    const float* embed = (const float*)d_in[1];
    const float* w_ih  = (const float*)d_in[2];
    const float* b_ih  = (const float*)d_in[3];
    const float* w_hh  = (const float*)d_in[4];
    const float* b_hh  = (const float*)d_in[5];
    const float* w_out = (const float*)d_in[6];
    const float* b_out = (const float*)d_in[7];
    float* out = (float*)d_out;

    size_t smem_lstm = (size_t)(16384 + 16384 + 2048 + 32) * sizeof(float);  // 139,392 B
    size_t smem_out  = (size_t)(8192 + Hn*On) * sizeof(float);               //  66,048 B
    cudaFuncSetAttribute(k_lstm, cudaFuncAttributeMaxDynamicSharedMemorySize, (int)smem_lstm);
    cudaFuncSetAttribute(k_out,  cudaFuncAttributeMaxDynamicSharedMemorySize, (int)smem_out);

    k_reset<<<128, 256>>>(x);
    k_token<<<Vn, G4>>>(embed, w_ih, b_ih, b_hh);
    k_lstm<<<Ln*CPL, NTHR, smem_lstm>>>(w_ih, b_ih, w_hh, b_hh, out);
    k_out<<<Tn, 256, smem_out>>>(w_out, b_out, out);
}

// round 8
// speedup vs baseline: 1.4637x; 1.4637x over previous
#include <cuda_runtime.h>
#include <cuda_bf16.h>
#include <mma.h>
#include <math.h>

using namespace nvcuda;

#define Ln 8
#define Tn 512
#define Hn 128
#define Bn 64
#define G4 512
#define Vn 65
#define On 65
#define CPL 16
#define NTHR 256
#define LDA 264          // padded k-stride (elements) for A and W tiles
#define LDG 36           // padded gate-row stride (floats)
#define OUT_MAIN (Bn*Tn*On)
#define OUT_H_BASE OUT_MAIN
#define OUT_C_BASE (OUT_MAIN + Ln*Bn*Hn)

// SMEM byte offsets (dynamic smem base is 16B aligned)
#define SM_GSM   0
#define SM_BIAS  9216
#define SM_AHI   9472
#define SM_ALO   (SM_AHI + 64*LDA*2)
#define SM_WHI   (SM_ALO + 64*LDA*2)
#define SM_WLO   (SM_WHI + 32*LDA*2)
#define SM_TOTAL (SM_WLO + 32*LDA*2)     // 110848 B

__device__ __align__(16) __nv_bfloat16 g_hh[2][(size_t)Ln*Tn*Bn*Hn]; // [arr][l][t][b][u]
__device__ __align__(16) __nv_bfloat16 g_emb[2][Vn*Hn];
__device__ __align__(16) __nv_bfloat16 g_W[2][Ln*CPL*32*256];        // [arr][l][gidx][n][k]
__device__ float    g_bias[Ln*G4];                                   // [l][gidx*32+n]
__device__ float    g_h7[(size_t)Tn*Hn*Bn];                          // [t][u][b]
__device__ int      g_xT[Tn*Bn];
__device__ unsigned g_cnt[Ln*Tn];

__device__ __forceinline__ unsigned ld_acq(const unsigned* p){
    unsigned v; asm volatile("ld.acquire.gpu.global.u32 %0, [%1];" : "=r"(v) : "l"(p) : "memory"); return v;
}
__device__ __forceinline__ void red_rel_add(unsigned* p){
    asm volatile("red.release.gpu.global.add.u32 [%0], 1;" :: "l"(p) : "memory");
}
__device__ __forceinline__ float fsig(float x){ return __fdividef(1.f, 1.f + __expf(-x)); }
__device__ __forceinline__ float ftanh(float x){ return 1.f - __fdividef(2.f, __expf(2.f*x)+1.f); }
__device__ __forceinline__ unsigned smaddr(const void* p){
    unsigned a; asm("{ .reg .u64 t; cvta.to.shared.u64 t, %1; cvt.u32.u64 %0, t; }" : "=r"(a) : "l"(p)); return a;
}
__device__ __forceinline__ void cpa16(unsigned dst, const void* src){
    asm volatile("cp.async.cg.shared.global [%0], [%1], 16;" :: "r"(dst), "l"(src) : "memory");
}
__device__ __forceinline__ void cpa_fence(){
    asm volatile("cp.async.commit_group;" ::: "memory");
    asm volatile("cp.async.wait_group 0;" ::: "memory");
}
__device__ __forceinline__ void sts_zero16(unsigned dst){
    asm volatile("st.shared.v4.b32 [%0], {%1,%1,%1,%1};" :: "r"(dst), "r"(0u) : "memory");
}

// ---------------------------------------------------------------------------
__global__ void k_reset(const int* __restrict__ x){
    int i = blockIdx.x*blockDim.x + threadIdx.x;
    if (i < Ln*Tn) g_cnt[i] = 0u;
    if (i < Tn*Bn){ int t = i/Bn, b = i%Bn; g_xT[i] = x[b*Tn + t]; }
}

// W reorder + hi/lo split: g_W[arr][l][gidx][n][k], n = ul*4 + gate
__global__ void k_prep_w(const float* __restrict__ w_ih, const float* __restrict__ w_hh,
                         const float* __restrict__ b_ih, const float* __restrict__ b_hh){
    int gid = blockIdx.x*256 + threadIdx.x;
    if (gid >= Ln*G4*256) return;
    int k = gid & 255, col = (gid>>8)&511, l = gid>>17;
    int gate = col>>7, u = col&127, gidx = u>>3, ul = u&7, n = ul*4+gate;
    float w = (k < Hn) ? w_ih[(l*Hn+k)*G4+col] : w_hh[(l*Hn+k-Hn)*G4+col];
    __nv_bfloat16 hi = __float2bfloat16_rn(w);
    int idx = ((l*CPL+gidx)*32 + n)*256 + k;
    g_W[0][idx] = hi;
    g_W[1][idx] = __float2bfloat16_rn(w - __bfloat162float(hi));
    if (k == 0) g_bias[l*G4 + gidx*32 + n] = b_ih[l*G4+col] + b_hh[l*G4+col];
}

__global__ void k_prep_e(const float* __restrict__ embed){
    int i = blockIdx.x*256 + threadIdx.x;
    if (i < Vn*Hn){
        float e = embed[i];
        __nv_bfloat16 hi = __float2bfloat16_rn(e);
        g_emb[0][i] = hi;
        g_emb[1][i] = __float2bfloat16_rn(e - __bfloat162float(hi));
    }
}

// ---------------------------------------------------------------------------
// Persistent wavefront LSTM; gate GEMM on tensor cores via wmma bf16 (3-term hi/lo).
__global__ void __launch_bounds__(NTHR, 1) k_lstm(float* __restrict__ out)
{
    extern __shared__ char smraw[];
    float* Gsm = (float*)(smraw + SM_GSM);                 // [64][LDG]
    float* Bsm = (float*)(smraw + SM_BIAS);                // [32]
    __nv_bfloat16* Ahi = (__nv_bfloat16*)(smraw + SM_AHI); // [64][LDA]
    __nv_bfloat16* Alo = (__nv_bfloat16*)(smraw + SM_ALO);
    __nv_bfloat16* Whi = (__nv_bfloat16*)(smraw + SM_WHI); // [32][LDA]
    __nv_bfloat16* Wlo = (__nv_bfloat16*)(smraw + SM_WLO);
    const unsigned sAhi = smaddr(Ahi), sAlo = smaddr(Alo);
    const unsigned sWhi = smaddr(Whi), sWlo = smaddr(Wlo);

    const int layer = blockIdx.x >> 4;
    const int gidx  = blockIdx.x & 15;
    const int tid   = threadIdx.x;
    const int wid   = tid >> 5;
    const int lane  = tid & 31;

    if (tid < 32) Bsm[tid] = g_bias[layer*G4 + gidx*32 + tid];

    // ---- stage W (once): [32][256] -> [32][LDA] hi/lo, via cp.async
    {
        const char* ws[2] = { (const char*)&g_W[0][((layer*CPL+gidx)*32)*256],
                              (const char*)&g_W[1][((layer*CPL+gidx)*32)*256] };
#pragma unroll
        for (int j = 0; j < 8; ++j){
            int id = j*NTHR + tid;           // 0..2047 chunks of 16B (8 bf16)
            int arr = id>>10, rem = id&1023;
            int n = rem>>5, k0 = (rem&31)*8;
            unsigned dst = (arr ? sWlo : sWhi) + (unsigned)(n*LDA + k0)*2u;
            cpa16(dst, ws[arr] + (n*256 + k0)*2);
        }
        cpa_fence();
    }
    __syncthreads();

    float cst[8];
#pragma unroll
    for (int u = 0; u < 8; ++u) cst[u] = 0.f;

    unsigned* cnt_own   = &g_cnt[layer*Tn];
    unsigned* cnt_below = (layer > 0) ? &g_cnt[(layer-1)*Tn] : nullptr;

    // wmma tile assignment: warp -> (row tile r = wid>>1, col tile c = wid&1)
    const int r16 = (wid >> 1) * 16;
    const int c16 = (wid & 1)  * 16;

    for (int t = 0; t < Tn; ++t){
        // ---- wait deps ----
        if (tid == 0 && layer > 0){ while (ld_acq(&cnt_below[t]) < CPL) __nanosleep(16); }
        if (tid == 32 && t > 0)   { while (ld_acq(&cnt_own[t-1]) < CPL) __nanosleep(16); }
        __syncthreads();

        // ---- stage A [64][256] hi/lo: k<128 input (emb/below-h), k>=128 own h[t-1]
        {
            const char* h0b[2]; const char* h1b[2];
            if (layer > 0){
                h0b[0] = (const char*)&g_hh[0][((size_t)(layer-1)*Tn + t)*Bn*Hn];
                h0b[1] = (const char*)&g_hh[1][((size_t)(layer-1)*Tn + t)*Bn*Hn];
            } else { h0b[0] = (const char*)g_emb[0]; h0b[1] = (const char*)g_emb[1]; }
            if (t > 0){
                h1b[0] = (const char*)&g_hh[0][((size_t)layer*Tn + (t-1))*Bn*Hn];
                h1b[1] = (const char*)&g_hh[1][((size_t)layer*Tn + (t-1))*Bn*Hn];
            }
            const int* xr = &g_xT[t*Bn];
#pragma unroll
            for (int j = 0; j < 16; ++j){
                int id = j*NTHR + tid;       // 0..4095 chunks of 16B
                int arr = id>>11, rem = id&2047;
                int b = rem>>5, k0 = (rem&31)*8;
                unsigned dst = (arr ? sAlo : sAhi) + (unsigned)(b*LDA + k0)*2u;
                if (k0 < 128){
                    const char* s = (layer==0) ? h0b[arr] + (xr[b]*Hn + k0)*2
                                               : h0b[arr] + (b*Hn + k0)*2;
                    cpa16(dst, s);
                } else if (t > 0){
                    cpa16(dst, h1b[arr] + (b*Hn + k0 - 128)*2);
                } else {
                    sts_zero16(dst);
                }
            }
            cpa_fence();
        }
        __syncthreads();

        // ---- tensor-core GEMM: gates[64][32] = A[64][256] x W[32][256]^T, 3-term
        {
            wmma::fragment<wmma::accumulator, 16,16,16, float> acc;
            wmma::fill_fragment(acc, 0.0f);
#pragma unroll
            for (int ks = 0; ks < 16; ++ks){
                wmma::fragment<wmma::matrix_a, 16,16,16, __nv_bfloat16, wmma::row_major> ah, al;
                wmma::fragment<wmma::matrix_b, 16,16,16, __nv_bfloat16, wmma::col_major> bh, bl;
                wmma::load_matrix_sync(ah, Ahi + r16*LDA + ks*16, LDA);
                wmma::load_matrix_sync(al, Alo + r16*LDA + ks*16, LDA);
                wmma::load_matrix_sync(bh, Whi + c16*LDA + ks*16, LDA);
                wmma::load_matrix_sync(bl, Wlo + c16*LDA + ks*16, LDA);
                wmma::mma_sync(acc, ah, bh, acc);
                wmma::mma_sync(acc, ah, bl, acc);
                wmma::mma_sync(acc, al, bh, acc);
            }
            wmma::store_matrix_sync(&Gsm[r16*LDG + c16], acc, LDG, wmma::mem_row_major);
        }
        __syncthreads();

        // ---- cell: warps 0,1 = batch rows 0..63; lane b holds 8 units
        if (wid < 2){
            const int b = wid*32 + lane;
            const float* gr = &Gsm[b*LDG];
            float hv[8];
#pragma unroll
            for (int u = 0; u < 8; ++u){
                float iv = fsig (gr[4*u+0] + Bsm[4*u+0]);
                float fv = fsig (gr[4*u+1] + Bsm[4*u+1]);
                float gv = ftanh(gr[4*u+2] + Bsm[4*u+2]);
                float ov = fsig (gr[4*u+3] + Bsm[4*u+3]);
                cst[u] = fv*cst[u] + iv*gv;
                hv[u]  = ov * ftanh(cst[u]);
            }
            unsigned hp[4], lp[4];
#pragma unroll
            for (int q = 0; q < 4; ++q){
                __nv_bfloat16 h0 = __float2bfloat16_rn(hv[2*q]);
                __nv_bfloat16 h1 = __float2bfloat16_rn(hv[2*q+1]);
                __nv_bfloat16 l0 = __float2bfloat16_rn(hv[2*q]   - __bfloat162float(h0));
                __nv_bfloat16 l1 = __float2bfloat16_rn(hv[2*q+1] - __bfloat162float(h1));
                hp[q] = ((unsigned)__bfloat16_as_ushort(h1)<<16) | __bfloat16_as_ushort(h0);
                lp[q] = ((unsigned)__bfloat16_as_ushort(l1)<<16) | __bfloat16_as_ushort(l0);
            }
            size_t ho = (((size_t)layer*Tn + t)*Bn + b)*Hn + gidx*8;
            *(uint4*)&g_hh[0][ho] = make_uint4(hp[0],hp[1],hp[2],hp[3]);
            *(uint4*)&g_hh[1][ho] = make_uint4(lp[0],lp[1],lp[2],lp[3]);
            if (layer == 7){
#pragma unroll
                for (int u = 0; u < 8; ++u)
                    g_h7[((size_t)t*Hn + gidx*8+u)*Bn + b] = hv[u];
            }
            if (t == Tn-1){
#pragma unroll
                for (int u = 0; u < 8; ++u){
                    out[OUT_H_BASE + (layer*Bn + b)*Hn + gidx*8+u] = hv[u];
                    out[OUT_C_BASE + (layer*Bn + b)*Hn + gidx*8+u] = cst[u];
                }
            }
        }
        __syncthreads();
        if (tid == 0) red_rel_add(&cnt_own[t]);
    }
}

// ---------------------------------------------------------------------------
__global__ void k_out(const float* __restrict__ w_out, const float* __restrict__ b_out,
                      float* __restrict__ out){
    extern __shared__ float sm[];
    float* Hs = sm;            // [128][64]
    float* Ws = sm + 8192;     // [128][65]
    int t = blockIdx.x, tid = threadIdx.x;
    const float4* s = (const float4*)&g_h7[(size_t)t*Hn*Bn];
    for (int i = tid; i < 2048; i += 256) ((float4*)Hs)[i] = s[i];
    for (int i = tid; i < Hn*On; i += 256) Ws[i] = w_out[i];
    __syncthreads();
    int b = tid & 63, og = tid >> 6;
    for (int o = og; o < On; o += 4){
        float acc = b_out[o];
#pragma unroll 8
        for (int k = 0; k < Hn; ++k) acc += Hs[k*Bn + b] * Ws[k*On + o];
        out[(b*Tn + t)*On + o] = acc;
    }
}

// ---------------------------------------------------------------------------
extern "C" void kernel_launch(void* const* d_in, const int* in_sizes, int n_in,
                              void* d_out, int out_size)
{
    const int*   x     = (const int*)  d_in[0];
    const float* embed = (const float*)d_in[1];
    const float* w_ih  = (const float*)d_in[2];
    const float* b_ih  = (const float*)d_in[3];
    const float* w_hh  = (const float*)d_in[4];
    const float* b_hh  = (const float*)d_in[5];
    const float* w_out = (const float*)d_in[6];
    const float* b_out = (const float*)d_in[7];
    float* out = (float*)d_out;

    size_t smem_lstm = SM_TOTAL;                                   // 110,848 B
    size_t smem_out  = (size_t)(8192 + Hn*On) * sizeof(float);
    cudaFuncSetAttribute(k_lstm, cudaFuncAttributeMaxDynamicSharedMemorySize, (int)smem_lstm);
    cudaFuncSetAttribute(k_out,  cudaFuncAttributeMaxDynamicSharedMemorySize, (int)smem_out);

    k_reset<<<128, 256>>>(x);
    k_prep_w<<<(Ln*G4*256)/256, 256>>>(w_ih, w_hh, b_ih, b_hh);
    k_prep_e<<<(Vn*Hn + 255)/256, 256>>>(embed);
    k_lstm<<<Ln*CPL, NTHR, smem_lstm>>>(out);
    k_out<<<Tn, 256, smem_out>>>(w_out, b_out, out);
}